// round 10
// baseline (speedup 1.0000x reference)
#include <cuda_runtime.h>
#include <cuda_bf16.h>

#define IN_DIM 128
#define OUT_DIM 64
#define N_MAX 100000
#define E_MAX 1600000
#define NEG_SLOPE 0.2f

// ---------------- scratch (static device globals: allocation-free) ----------
__device__ float d_h[(size_t)N_MAX * OUT_DIM];   // transformed features
__device__ float d_as[N_MAX];                    // h @ att_src
__device__ float d_ad[N_MAX];                    // h @ att_dst
__device__ int   d_deg[N_MAX];                   // in-degree histogram
__device__ int   d_excl[N_MAX];                  // tile-local exclusive prefix
__device__ int   d_bsum[128];                    // per-tile totals
__device__ int   d_boff[128];                    // per-tile exclusive offsets
__device__ int   d_start[N_MAX + 1];             // CSR row offsets (by dst)
__device__ int   d_cursor[N_MAX];                // placement cursors
__device__ int2  d_rec[E_MAX];                   // bucketed (src, w-as-bits)
__device__ int   d_is64;                         // edge_index dtype flag

__device__ __forceinline__ float lrelu(float v) {
    return v > 0.f ? v : NEG_SLOPE * v;
}

// ---------------- K0: detect edge_index element width ------------------------
__global__ void k0_detect(const long long* __restrict__ ei, int N)
{
    int ok64 = 1;
    for (int i = 0; i < 64; i++) {
        long long v = ei[i];
        if (v < 0 || v >= (long long)N) { ok64 = 0; break; }
    }
    d_is64 = ok64;
}

// ---------------- K1: h = x @ W (2 rows x 4 cols per thread) -----------------
__global__ __launch_bounds__(256) void k1_gemm(
    const float* __restrict__ x, const float* __restrict__ W,
    const float* __restrict__ att_src, const float* __restrict__ att_dst, int N)
{
    __shared__ float Ws[IN_DIM * OUT_DIM];        // 32 KB, row-major [k][64]
    __shared__ float xs[32][IN_DIM + 1];          // 16.5 KB

    int t = threadIdx.x;
    for (int i = t; i < IN_DIM * OUT_DIM; i += 256) Ws[i] = W[i];

    int row0 = blockIdx.x * 32;
    for (int i = t; i < 32 * IN_DIM; i += 256) {
        int r = i >> 7, k = i & 127;
        int gr = row0 + r;
        xs[r][k] = (gr < N) ? x[(size_t)gr * IN_DIM + k] : 0.f;
    }
    __syncthreads();

    int r  = t >> 4;          // local row pair base: rows r and r+16
    int cg = t & 15;          // col group (4 cols each)
    int gr0 = row0 + r;
    int gr1 = row0 + r + 16;

    const float4* W4 = reinterpret_cast<const float4*>(Ws);
    float4 a0 = make_float4(0.f, 0.f, 0.f, 0.f);
    float4 a1 = make_float4(0.f, 0.f, 0.f, 0.f);
#pragma unroll 8
    for (int k = 0; k < IN_DIM; k++) {
        float4 w = W4[k * 16 + cg];
        float x0 = xs[r][k];
        float x1 = xs[r + 16][k];
        a0.x = fmaf(x0, w.x, a0.x); a0.y = fmaf(x0, w.y, a0.y);
        a0.z = fmaf(x0, w.z, a0.z); a0.w = fmaf(x0, w.w, a0.w);
        a1.x = fmaf(x1, w.x, a1.x); a1.y = fmaf(x1, w.y, a1.y);
        a1.z = fmaf(x1, w.z, a1.z); a1.w = fmaf(x1, w.w, a1.w);
    }
    if (gr0 < N) reinterpret_cast<float4*>(d_h)[(size_t)gr0 * 16 + cg] = a0;
    if (gr1 < N) reinterpret_cast<float4*>(d_h)[(size_t)gr1 * 16 + cg] = a1;

    float4 As4 = reinterpret_cast<const float4*>(att_src)[cg];
    float4 Ad4 = reinterpret_cast<const float4*>(att_dst)[cg];
    float ps0 = a0.x * As4.x + a0.y * As4.y + a0.z * As4.z + a0.w * As4.w;
    float pd0 = a0.x * Ad4.x + a0.y * Ad4.y + a0.z * Ad4.z + a0.w * Ad4.w;
    float ps1 = a1.x * As4.x + a1.y * As4.y + a1.z * As4.z + a1.w * As4.w;
    float pd1 = a1.x * Ad4.x + a1.y * Ad4.y + a1.z * Ad4.z + a1.w * Ad4.w;
#pragma unroll
    for (int o = 8; o; o >>= 1) {
        ps0 += __shfl_down_sync(0xffffffffu, ps0, o);
        pd0 += __shfl_down_sync(0xffffffffu, pd0, o);
        ps1 += __shfl_down_sync(0xffffffffu, ps1, o);
        pd1 += __shfl_down_sync(0xffffffffu, pd1, o);
    }
    if (cg == 0) {
        if (gr0 < N) { d_as[gr0] = ps0; d_ad[gr0] = pd0; d_deg[gr0] = 0; }
        if (gr1 < N) { d_as[gr1] = ps1; d_ad[gr1] = pd1; d_deg[gr1] = 0; }
    }
}

// ---------------- K2a: dst-degree histogram, 4 edges/thread ------------------
__global__ __launch_bounds__(256) void k2a_hist(
    const void* __restrict__ ei_raw, int E, int N)
{
    int q = blockIdx.x * blockDim.x + threadIdx.x;   // quad index
    int base = q * 4;
    if (base >= E) return;

    if (!d_is64 && base + 4 <= E) {
        const int4* p4 = reinterpret_cast<const int4*>((const int*)ei_raw + (size_t)E);
        int4 d4 = p4[q];
        int a = d4.x, b = d4.y, c = d4.z, d = d4.w;
        if ((unsigned)a >= (unsigned)N) a = 0;
        if ((unsigned)b >= (unsigned)N) b = 0;
        if ((unsigned)c >= (unsigned)N) c = 0;
        if ((unsigned)d >= (unsigned)N) d = 0;
        atomicAdd(&d_deg[a], 1);
        atomicAdd(&d_deg[b], 1);
        atomicAdd(&d_deg[c], 1);
        atomicAdd(&d_deg[d], 1);
    } else {
        for (int i = base; i < min(base + 4, E); i++) {
            int d;
            if (d_is64) d = (int)((const long long*)ei_raw)[(size_t)E + i];
            else        d = ((const int*)ei_raw)[(size_t)E + i];
            if ((unsigned)d >= (unsigned)N) d = 0;
            atomicAdd(&d_deg[d], 1);
        }
    }
}

// ---------------- kS1/kS2/kS3: parallel 3-stage exclusive scan ---------------
__global__ __launch_bounds__(1024) void kS1_tile_scan(int N)
{
    __shared__ int sh[1024];
    int t = threadIdx.x;
    int gi = blockIdx.x * 1024 + t;
    int v = (gi < N) ? d_deg[gi] : 0;
    sh[t] = v;
    __syncthreads();
#pragma unroll
    for (int off = 1; off < 1024; off <<= 1) {
        int u = (t >= off) ? sh[t - off] : 0;
        __syncthreads();
        sh[t] += u;
        __syncthreads();
    }
    if (gi < N) d_excl[gi] = sh[t] - v;
    if (t == 1023) d_bsum[blockIdx.x] = sh[t];
}

__global__ __launch_bounds__(128) void kS2_block_scan(int nTiles)
{
    __shared__ int sh[128];
    int t = threadIdx.x;
    int v = (t < nTiles) ? d_bsum[t] : 0;
    sh[t] = v;
    __syncthreads();
#pragma unroll
    for (int off = 1; off < 128; off <<= 1) {
        int u = (t >= off) ? sh[t - off] : 0;
        __syncthreads();
        sh[t] += u;
        __syncthreads();
    }
    if (t < nTiles) d_boff[t] = sh[t] - v;
}

__global__ __launch_bounds__(256) void kS3_finalize(int N, int E)
{
    int i = blockIdx.x * blockDim.x + threadIdx.x;
    if (i < N) {
        int s = d_excl[i] + d_boff[i >> 10];
        d_start[i]  = s;
        d_cursor[i] = s;
    }
    if (i == 0) d_start[N] = E;
}

// ---------------- K2c: decode + weight + place, 4 edges/thread ---------------
__global__ __launch_bounds__(256) void k2c_place(
    const void* __restrict__ ei_raw, int E, int N)
{
    int q = blockIdx.x * blockDim.x + threadIdx.x;
    int base = q * 4;
    if (base >= E) return;

    if (!d_is64 && base + 4 <= E) {
        const int* pi = (const int*)ei_raw;
        int4 s4 = reinterpret_cast<const int4*>(pi)[q];
        int4 t4 = reinterpret_cast<const int4*>(pi + (size_t)E)[q];
        int s[4] = {s4.x, s4.y, s4.z, s4.w};
        int d[4] = {t4.x, t4.y, t4.z, t4.w};
#pragma unroll
        for (int k = 0; k < 4; k++) {
            if ((unsigned)s[k] >= (unsigned)N) s[k] = 0;
            if ((unsigned)d[k] >= (unsigned)N) d[k] = 0;
        }
        float as0 = d_as[s[0]], as1 = d_as[s[1]], as2 = d_as[s[2]], as3 = d_as[s[3]];
        float ad0 = d_ad[d[0]], ad1 = d_ad[d[1]], ad2 = d_ad[d[2]], ad3 = d_ad[d[3]];
        float w0 = __expf(lrelu(as0 + ad0));
        float w1 = __expf(lrelu(as1 + ad1));
        float w2 = __expf(lrelu(as2 + ad2));
        float w3 = __expf(lrelu(as3 + ad3));
        int p0 = atomicAdd(&d_cursor[d[0]], 1);
        int p1 = atomicAdd(&d_cursor[d[1]], 1);
        int p2 = atomicAdd(&d_cursor[d[2]], 1);
        int p3 = atomicAdd(&d_cursor[d[3]], 1);
        d_rec[p0] = make_int2(s[0], __float_as_int(w0));
        d_rec[p1] = make_int2(s[1], __float_as_int(w1));
        d_rec[p2] = make_int2(s[2], __float_as_int(w2));
        d_rec[p3] = make_int2(s[3], __float_as_int(w3));
    } else {
        for (int i = base; i < min(base + 4, E); i++) {
            int s, d;
            if (d_is64) {
                const long long* p = (const long long*)ei_raw;
                s = (int)p[i];
                d = (int)p[(size_t)E + i];
            } else {
                const int* p = (const int*)ei_raw;
                s = p[i];
                d = p[(size_t)E + i];
            }
            if ((unsigned)s >= (unsigned)N) s = 0;
            if ((unsigned)d >= (unsigned)N) d = 0;
            float w = __expf(lrelu(d_as[s] + d_ad[d]));
            int p = atomicAdd(&d_cursor[d], 1);
            d_rec[p] = make_int2(s, __float_as_int(w));
        }
    }
}

// ---------------- K5: per-node gather-aggregate (one warp per node) ----------
// Records loaded by all lanes directly (L1 broadcast); 8-way manual unroll
// keeps 8 independent 256B h-gathers in flight.
__global__ __launch_bounds__(256) void k5_gather(
    float2* __restrict__ out, const float* __restrict__ bias, int N)
{
    int t = threadIdx.x;
    int warp = t >> 5, lane = t & 31;
    int n = blockIdx.x * 8 + warp;
    if (n >= N) return;

    const float2* h2 = reinterpret_cast<const float2*>(d_h);

    float wself = __expf(lrelu(d_as[n] + d_ad[n]));
    float2 hv = h2[(size_t)n * 32 + lane];
    float accx = wself * hv.x;
    float accy = wself * hv.y;
    float wsum = wself;

    int beg = d_start[n], end = d_start[n + 1];
    int j = beg;
    for (; j + 8 <= end; j += 8) {
        int2 r0 = d_rec[j + 0];
        int2 r1 = d_rec[j + 1];
        int2 r2 = d_rec[j + 2];
        int2 r3 = d_rec[j + 3];
        int2 r4 = d_rec[j + 4];
        int2 r5 = d_rec[j + 5];
        int2 r6 = d_rec[j + 6];
        int2 r7 = d_rec[j + 7];
        float2 v0 = h2[(size_t)r0.x * 32 + lane];
        float2 v1 = h2[(size_t)r1.x * 32 + lane];
        float2 v2 = h2[(size_t)r2.x * 32 + lane];
        float2 v3 = h2[(size_t)r3.x * 32 + lane];
        float2 v4 = h2[(size_t)r4.x * 32 + lane];
        float2 v5 = h2[(size_t)r5.x * 32 + lane];
        float2 v6 = h2[(size_t)r6.x * 32 + lane];
        float2 v7 = h2[(size_t)r7.x * 32 + lane];
        float w0 = __int_as_float(r0.y), w1 = __int_as_float(r1.y);
        float w2 = __int_as_float(r2.y), w3 = __int_as_float(r3.y);
        float w4 = __int_as_float(r4.y), w5 = __int_as_float(r5.y);
        float w6 = __int_as_float(r6.y), w7 = __int_as_float(r7.y);
        accx = fmaf(w0, v0.x, accx); accy = fmaf(w0, v0.y, accy);
        accx = fmaf(w1, v1.x, accx); accy = fmaf(w1, v1.y, accy);
        accx = fmaf(w2, v2.x, accx); accy = fmaf(w2, v2.y, accy);
        accx = fmaf(w3, v3.x, accx); accy = fmaf(w3, v3.y, accy);
        accx = fmaf(w4, v4.x, accx); accy = fmaf(w4, v4.y, accy);
        accx = fmaf(w5, v5.x, accx); accy = fmaf(w5, v5.y, accy);
        accx = fmaf(w6, v6.x, accx); accy = fmaf(w6, v6.y, accy);
        accx = fmaf(w7, v7.x, accx); accy = fmaf(w7, v7.y, accy);
        wsum += (w0 + w1 + w2 + w3) + (w4 + w5 + w6 + w7);
    }
    for (; j + 4 <= end; j += 4) {
        int2 r0 = d_rec[j + 0];
        int2 r1 = d_rec[j + 1];
        int2 r2 = d_rec[j + 2];
        int2 r3 = d_rec[j + 3];
        float2 v0 = h2[(size_t)r0.x * 32 + lane];
        float2 v1 = h2[(size_t)r1.x * 32 + lane];
        float2 v2 = h2[(size_t)r2.x * 32 + lane];
        float2 v3 = h2[(size_t)r3.x * 32 + lane];
        float w0 = __int_as_float(r0.y), w1 = __int_as_float(r1.y);
        float w2 = __int_as_float(r2.y), w3 = __int_as_float(r3.y);
        accx = fmaf(w0, v0.x, accx); accy = fmaf(w0, v0.y, accy);
        accx = fmaf(w1, v1.x, accx); accy = fmaf(w1, v1.y, accy);
        accx = fmaf(w2, v2.x, accx); accy = fmaf(w2, v2.y, accy);
        accx = fmaf(w3, v3.x, accx); accy = fmaf(w3, v3.y, accy);
        wsum += w0 + w1 + w2 + w3;
    }
    for (; j < end; j++) {
        int2 r = d_rec[j];
        float w = __int_as_float(r.y);
        float2 v = h2[(size_t)r.x * 32 + lane];
        accx = fmaf(w, v.x, accx);
        accy = fmaf(w, v.y, accy);
        wsum += w;
    }

    float inv = 1.f / wsum;
    float2 b = reinterpret_cast<const float2*>(bias)[lane];
    out[(size_t)n * 32 + lane] = make_float2(accx * inv + b.x, accy * inv + b.y);
}

// ---------------- launch ------------------------------------------------------
extern "C" void kernel_launch(void* const* d_in, const int* in_sizes, int n_in,
                              void* d_out, int out_size)
{
    const float* x    = (const float*)d_in[0];
    const void*  ei   = d_in[1];
    const float* W    = (const float*)d_in[2];
    const float* asrc = (const float*)d_in[3];
    const float* adst = (const float*)d_in[4];
    const float* bias = (const float*)d_in[5];
    float*       out  = (float*)d_out;

    int N = in_sizes[0] / IN_DIM;
    int E = in_sizes[1] / 2;
    int nTiles = (N + 1023) / 1024;    // <= 128 for N <= 100k
    int nQuads = (E + 3) / 4;

    k0_detect<<<1, 1>>>((const long long*)ei, N);
    k1_gemm<<<(N + 31) / 32, 256>>>(x, W, asrc, adst, N);
    k2a_hist<<<(nQuads + 255) / 256, 256>>>(ei, E, N);
    kS1_tile_scan<<<nTiles, 1024>>>(N);
    kS2_block_scan<<<1, 128>>>(nTiles);
    kS3_finalize<<<(N + 255) / 256, 256>>>(N, E);
    k2c_place<<<(nQuads + 255) / 256, 256>>>(ei, E, N);
    k5_gather<<<(N + 7) / 8, 256>>>((float2*)out, bias, N);
}

// round 11
// speedup vs baseline: 1.0676x; 1.0676x over previous
#include <cuda_runtime.h>
#include <cuda_bf16.h>

#define IN_DIM 128
#define OUT_DIM 64
#define N_MAX 100000
#define E_MAX 1600000
#define NEG_SLOPE 0.2f

// ---------------- scratch (static device globals: allocation-free) ----------
__device__ float d_h[(size_t)N_MAX * OUT_DIM];   // transformed features
__device__ float d_as[N_MAX];                    // h @ att_src
__device__ float d_ad[N_MAX];                    // h @ att_dst
__device__ int   d_deg[N_MAX];                   // in-degree histogram
__device__ int   d_excl[N_MAX];                  // tile-local exclusive prefix
__device__ int   d_bsum[128];                    // per-tile totals
__device__ int   d_start[N_MAX + 1];             // CSR row offsets (by dst)
__device__ int   d_cursor[N_MAX];                // placement cursors
__device__ int2  d_rec[E_MAX];                   // bucketed (src, w-as-bits)
__device__ int   d_is64;                         // edge_index dtype flag

__device__ __forceinline__ float lrelu(float v) {
    return v > 0.f ? v : NEG_SLOPE * v;
}

// ---------------- K0: detect edge_index element width ------------------------
__global__ void k0_detect(const long long* __restrict__ ei, int N)
{
    int ok64 = 1;
    for (int i = 0; i < 64; i++) {
        long long v = ei[i];
        if (v < 0 || v >= (long long)N) { ok64 = 0; break; }
    }
    d_is64 = ok64;
}

// ---------------- K2a: dst-degree histogram (1 edge/thread, R9 form) ---------
__global__ __launch_bounds__(256) void k2a_hist(
    const void* __restrict__ ei_raw, int E, int N)
{
    int i = blockIdx.x * blockDim.x + threadIdx.x;
    if (i >= E) return;
    int d;
    if (d_is64) {
        d = (int)((const long long*)ei_raw)[(size_t)E + i];
    } else {
        d = ((const int*)ei_raw)[(size_t)E + i];
    }
    if ((unsigned)d >= (unsigned)N) d = 0;
    atomicAdd(&d_deg[d], 1);
}

// ---------------- kS1: per-tile scan ------------------------------------------
__global__ __launch_bounds__(1024) void kS1_tile_scan(int N)
{
    __shared__ int sh[1024];
    int t = threadIdx.x;
    int gi = blockIdx.x * 1024 + t;
    int v = (gi < N) ? d_deg[gi] : 0;
    sh[t] = v;
    __syncthreads();
#pragma unroll
    for (int off = 1; off < 1024; off <<= 1) {
        int u = (t >= off) ? sh[t - off] : 0;
        __syncthreads();
        sh[t] += u;
        __syncthreads();
    }
    if (gi < N) d_excl[gi] = sh[t] - v;
    if (t == 1023) d_bsum[blockIdx.x] = sh[t];
}

// ---------------- K1: h = x @ W (2 rows x 4 cols per thread) -----------------
__global__ __launch_bounds__(256) void k1_gemm(
    const float* __restrict__ x, const float* __restrict__ W,
    const float* __restrict__ att_src, const float* __restrict__ att_dst, int N)
{
    __shared__ float Ws[IN_DIM * OUT_DIM];        // 32 KB, row-major [k][64]
    __shared__ float xs[32][IN_DIM + 1];          // 16.5 KB

    int t = threadIdx.x;
    for (int i = t; i < IN_DIM * OUT_DIM; i += 256) Ws[i] = W[i];

    int row0 = blockIdx.x * 32;
    for (int i = t; i < 32 * IN_DIM; i += 256) {
        int r = i >> 7, k = i & 127;
        int gr = row0 + r;
        xs[r][k] = (gr < N) ? x[(size_t)gr * IN_DIM + k] : 0.f;
    }
    __syncthreads();

    int r  = t >> 4;          // local row pair base: rows r and r+16
    int cg = t & 15;          // col group (4 cols each)
    int gr0 = row0 + r;
    int gr1 = row0 + r + 16;

    const float4* W4 = reinterpret_cast<const float4*>(Ws);
    float4 a0 = make_float4(0.f, 0.f, 0.f, 0.f);
    float4 a1 = make_float4(0.f, 0.f, 0.f, 0.f);
#pragma unroll 8
    for (int k = 0; k < IN_DIM; k++) {
        float4 w = W4[k * 16 + cg];
        float x0 = xs[r][k];
        float x1 = xs[r + 16][k];
        a0.x = fmaf(x0, w.x, a0.x); a0.y = fmaf(x0, w.y, a0.y);
        a0.z = fmaf(x0, w.z, a0.z); a0.w = fmaf(x0, w.w, a0.w);
        a1.x = fmaf(x1, w.x, a1.x); a1.y = fmaf(x1, w.y, a1.y);
        a1.z = fmaf(x1, w.z, a1.z); a1.w = fmaf(x1, w.w, a1.w);
    }
    if (gr0 < N) reinterpret_cast<float4*>(d_h)[(size_t)gr0 * 16 + cg] = a0;
    if (gr1 < N) reinterpret_cast<float4*>(d_h)[(size_t)gr1 * 16 + cg] = a1;

    float4 As4 = reinterpret_cast<const float4*>(att_src)[cg];
    float4 Ad4 = reinterpret_cast<const float4*>(att_dst)[cg];
    float ps0 = a0.x * As4.x + a0.y * As4.y + a0.z * As4.z + a0.w * As4.w;
    float pd0 = a0.x * Ad4.x + a0.y * Ad4.y + a0.z * Ad4.z + a0.w * Ad4.w;
    float ps1 = a1.x * As4.x + a1.y * As4.y + a1.z * As4.z + a1.w * As4.w;
    float pd1 = a1.x * Ad4.x + a1.y * Ad4.y + a1.z * Ad4.z + a1.w * Ad4.w;
#pragma unroll
    for (int o = 8; o; o >>= 1) {
        ps0 += __shfl_down_sync(0xffffffffu, ps0, o);
        pd0 += __shfl_down_sync(0xffffffffu, pd0, o);
        ps1 += __shfl_down_sync(0xffffffffu, ps1, o);
        pd1 += __shfl_down_sync(0xffffffffu, pd1, o);
    }
    if (cg == 0) {
        if (gr0 < N) { d_as[gr0] = ps0; d_ad[gr0] = pd0; }
        if (gr1 < N) { d_as[gr1] = ps1; d_ad[gr1] = pd1; }
    }
}

// ---------------- kS23: finalize offsets (block-local scan of tile sums) -----
// Each block redundantly scans the <=128 tile sums in smem (cheap), then
// applies offsets. Also zeroes d_deg for the next graph replay.
__global__ __launch_bounds__(256) void kS23_finalize(int N, int E, int nTiles)
{
    __shared__ int sh[128];
    int t = threadIdx.x;
    if (t < 128) sh[t] = (t < nTiles) ? d_bsum[t] : 0;
    __syncthreads();
    // serial scan by thread 0 over <=128 entries (fast in smem, no sync dance)
    if (t == 0) {
        int run = 0;
        for (int i = 0; i < nTiles; i++) {
            int v = sh[i];
            sh[i] = run;
            run += v;
        }
    }
    __syncthreads();

    int i = blockIdx.x * blockDim.x + t;
    if (i < N) {
        int s = d_excl[i] + sh[i >> 10];
        d_start[i]  = s;
        d_cursor[i] = s;
        d_deg[i]    = 0;        // reset histogram for next replay
    }
    if (i == 0) d_start[N] = E;
}

// ---------------- K2c: decode + weight + place (1 edge/thread, R9 form) ------
__global__ __launch_bounds__(256) void k2c_place(
    const void* __restrict__ ei_raw, int E, int N)
{
    int i = blockIdx.x * blockDim.x + threadIdx.x;
    if (i >= E) return;
    int s, d;
    if (d_is64) {
        const long long* p = (const long long*)ei_raw;
        s = (int)p[i];
        d = (int)p[(size_t)E + i];
    } else {
        const int* p = (const int*)ei_raw;
        s = p[i];
        d = p[(size_t)E + i];
    }
    if ((unsigned)s >= (unsigned)N) s = 0;
    if ((unsigned)d >= (unsigned)N) d = 0;

    float w = __expf(lrelu(d_as[s] + d_ad[d]));
    int p = atomicAdd(&d_cursor[d], 1);
    d_rec[p] = make_int2(s, __float_as_int(w));
}

// ---------------- K5: gather-aggregate, half-warp float4, 2 edges/warp-step --
// Lanes 0-15 process edge j, lanes 16-31 edge j+1; each lane gathers float4
// (16B x 16 lanes = full 256B row). Pair-unroll x2 -> 4 gathers in flight.
__global__ __launch_bounds__(256) void k5_gather(
    float4* __restrict__ out, const float* __restrict__ bias, int N)
{
    int t = threadIdx.x;
    int warp = t >> 5, lane = t & 31;
    int half = lane >> 4;           // 0 or 1
    int hl   = lane & 15;           // float4 slot: cols hl*4..hl*4+3
    int n = blockIdx.x * 8 + warp;
    if (n >= N) return;

    const float4* h4 = reinterpret_cast<const float4*>(d_h);

    float wself = __expf(lrelu(d_as[n] + d_ad[n]));
    float4 hv = h4[(size_t)n * 16 + hl];
    float4 acc;
    float wsum;
    if (half == 0) {
        acc = make_float4(wself * hv.x, wself * hv.y, wself * hv.z, wself * hv.w);
        wsum = wself;
    } else {
        acc = make_float4(0.f, 0.f, 0.f, 0.f);
        wsum = 0.f;
    }

    int beg = d_start[n], end = d_start[n + 1];
    int j = beg;
    for (; j + 4 <= end; j += 4) {
        int2 rA = d_rec[j + half];
        int2 rB = d_rec[j + 2 + half];
        float4 vA = h4[(size_t)rA.x * 16 + hl];
        float4 vB = h4[(size_t)rB.x * 16 + hl];
        float wA = __int_as_float(rA.y);
        float wB = __int_as_float(rB.y);
        acc.x = fmaf(wA, vA.x, acc.x); acc.y = fmaf(wA, vA.y, acc.y);
        acc.z = fmaf(wA, vA.z, acc.z); acc.w = fmaf(wA, vA.w, acc.w);
        acc.x = fmaf(wB, vB.x, acc.x); acc.y = fmaf(wB, vB.y, acc.y);
        acc.z = fmaf(wB, vB.z, acc.z); acc.w = fmaf(wB, vB.w, acc.w);
        wsum += wA + wB;
    }
    if (j + 2 <= end) {
        int2 r = d_rec[j + half];
        float4 v = h4[(size_t)r.x * 16 + hl];
        float w = __int_as_float(r.y);
        acc.x = fmaf(w, v.x, acc.x); acc.y = fmaf(w, v.y, acc.y);
        acc.z = fmaf(w, v.z, acc.z); acc.w = fmaf(w, v.w, acc.w);
        wsum += w;
        j += 2;
    }
    if (j < end) {                       // single leftover edge: half 0 only
        int2 r = d_rec[j];
        float w = (half == 0) ? __int_as_float(r.y) : 0.f;
        float4 v = h4[(size_t)r.x * 16 + hl];
        acc.x = fmaf(w, v.x, acc.x); acc.y = fmaf(w, v.y, acc.y);
        acc.z = fmaf(w, v.z, acc.z); acc.w = fmaf(w, v.w, acc.w);
        wsum += w;
    }

    // combine halves (lane i <-> lane i+16 hold same columns)
    wsum  += __shfl_xor_sync(0xffffffffu, wsum,  16);
    acc.x += __shfl_xor_sync(0xffffffffu, acc.x, 16);
    acc.y += __shfl_xor_sync(0xffffffffu, acc.y, 16);
    acc.z += __shfl_xor_sync(0xffffffffu, acc.z, 16);
    acc.w += __shfl_xor_sync(0xffffffffu, acc.w, 16);

    if (half == 0) {
        float inv = 1.f / wsum;
        float4 b = reinterpret_cast<const float4*>(bias)[hl];
        out[(size_t)n * 16 + hl] = make_float4(acc.x * inv + b.x,
                                               acc.y * inv + b.y,
                                               acc.z * inv + b.z,
                                               acc.w * inv + b.w);
    }
}

// ---------------- launch ------------------------------------------------------
extern "C" void kernel_launch(void* const* d_in, const int* in_sizes, int n_in,
                              void* d_out, int out_size)
{
    const float* x    = (const float*)d_in[0];
    const void*  ei   = d_in[1];
    const float* W    = (const float*)d_in[2];
    const float* asrc = (const float*)d_in[3];
    const float* adst = (const float*)d_in[4];
    const float* bias = (const float*)d_in[5];
    float*       out  = (float*)d_out;

    int N = in_sizes[0] / IN_DIM;
    int E = in_sizes[1] / 2;
    int nTiles = (N + 1023) / 1024;    // <= 128 for N <= 100k

    k0_detect<<<1, 1>>>((const long long*)ei, N);
    k2a_hist<<<(E + 255) / 256, 256>>>(ei, E, N);
    kS1_tile_scan<<<nTiles, 1024>>>(N);
    k1_gemm<<<(N + 31) / 32, 256>>>(x, W, asrc, adst, N);   // 4th: profiled
    kS23_finalize<<<(N + 255) / 256, 256>>>(N, E, nTiles);
    k2c_place<<<(E + 255) / 256, 256>>>(ei, E, N);
    k5_gather<<<(N + 7) / 8, 256>>>((float4*)out, bias, N);
}

// round 12
// speedup vs baseline: 1.5142x; 1.4183x over previous
#include <cuda_runtime.h>
#include <cuda_bf16.h>

#define IN_DIM 128
#define OUT_DIM 64
#define N_MAX 100000
#define E_MAX 1600000
#define NEG_SLOPE 0.2f

// ---------------- scratch (static device globals: allocation-free) ----------
__device__ float d_h[(size_t)N_MAX * OUT_DIM];   // transformed features
__device__ float d_as[N_MAX];                    // h @ att_src
__device__ float d_ad[N_MAX];                    // h @ att_dst
__device__ int   d_deg[N_MAX];                   // in-degree histogram
__device__ int   d_excl[N_MAX];                  // tile-local exclusive prefix
__device__ int   d_bsum[128];                    // per-tile totals
__device__ int   d_start[N_MAX + 1];             // CSR row offsets (by dst)
__device__ int   d_cursor[N_MAX];                // placement cursors
__device__ int2  d_rec[E_MAX];                   // bucketed (src, w-as-bits)
__device__ int   d_is64;                         // edge_index dtype flag

__device__ __forceinline__ float lrelu(float v) {
    return v > 0.f ? v : NEG_SLOPE * v;
}

// ---------------- K0: detect edge_index element width ------------------------
__global__ void k0_detect(const long long* __restrict__ ei, int N)
{
    int ok64 = 1;
    for (int i = 0; i < 64; i++) {
        long long v = ei[i];
        if (v < 0 || v >= (long long)N) { ok64 = 0; break; }
    }
    d_is64 = ok64;
}

// ---------------- K2a: dst-degree histogram ----------------------------------
__global__ __launch_bounds__(256) void k2a_hist(
    const void* __restrict__ ei_raw, int E, int N)
{
    int i = blockIdx.x * blockDim.x + threadIdx.x;
    if (i >= E) return;
    int d;
    if (d_is64) {
        d = (int)((const long long*)ei_raw)[(size_t)E + i];
    } else {
        d = ((const int*)ei_raw)[(size_t)E + i];
    }
    if ((unsigned)d >= (unsigned)N) d = 0;
    atomicAdd(&d_deg[d], 1);
}

// ---------------- kS1: per-tile scan ------------------------------------------
__global__ __launch_bounds__(1024) void kS1_tile_scan(int N)
{
    __shared__ int sh[1024];
    int t = threadIdx.x;
    int gi = blockIdx.x * 1024 + t;
    int v = (gi < N) ? d_deg[gi] : 0;
    sh[t] = v;
    __syncthreads();
#pragma unroll
    for (int off = 1; off < 1024; off <<= 1) {
        int u = (t >= off) ? sh[t - off] : 0;
        __syncthreads();
        sh[t] += u;
        __syncthreads();
    }
    if (gi < N) d_excl[gi] = sh[t] - v;
    if (t == 1023) d_bsum[blockIdx.x] = sh[t];
}

// ---------------- K1: register-blocked GEMM, 64x64 tile, 4x4 per thread ------
// xs staged TRANSPOSED (xs[k][row]) so 4 rows = one LDS.128; W chunk as
// Wc[k][col] so 4 cols = one LDS.128. 2 LDS.128 per 16 FMAs.
__global__ __launch_bounds__(256) void k1_gemm(
    const float* __restrict__ x, const float* __restrict__ W,
    const float* __restrict__ att_src, const float* __restrict__ att_dst, int N)
{
    __shared__ float Wc[64][64];        // 16 KB   k-chunk of W
    __shared__ float xs[64][68];        // 17 KB   transposed x chunk (pad 4)

    int t  = threadIdx.x;
    int cg = t & 15;          // col group: cols cg*4 .. cg*4+3
    int rg = t >> 4;          // row group: rows rg*4 .. rg*4+3
    int row0 = blockIdx.x * 64;

    float4 acc0 = make_float4(0.f, 0.f, 0.f, 0.f);
    float4 acc1 = make_float4(0.f, 0.f, 0.f, 0.f);
    float4 acc2 = make_float4(0.f, 0.f, 0.f, 0.f);
    float4 acc3 = make_float4(0.f, 0.f, 0.f, 0.f);

#pragma unroll
    for (int kc = 0; kc < 2; kc++) {
        // load W chunk: rows kc*64..+63 of W[k][64] -> Wc[kk][c]
        {
            const float4* Wg = reinterpret_cast<const float4*>(W + kc * 64 * OUT_DIM);
            for (int i = t; i < 64 * 16; i += 256) {
                int kk = i >> 4, c4 = i & 15;
                *reinterpret_cast<float4*>(&Wc[kk][c4 * 4]) = Wg[i];
            }
        }
        // load x chunk transposed: x[gr][kc*64 + kk] -> xs[kk][r]
        {
            for (int i = t; i < 64 * 16; i += 256) {
                int r = i >> 4, k4 = i & 15;
                int gr = row0 + r;
                float4 xv = (gr < N)
                    ? reinterpret_cast<const float4*>(x)[(size_t)gr * 32 + kc * 16 + k4]
                    : make_float4(0.f, 0.f, 0.f, 0.f);
                xs[k4 * 4 + 0][r] = xv.x;
                xs[k4 * 4 + 1][r] = xv.y;
                xs[k4 * 4 + 2][r] = xv.z;
                xs[k4 * 4 + 3][r] = xv.w;
            }
        }
        __syncthreads();

#pragma unroll 16
        for (int kk = 0; kk < 64; kk++) {
            float4 xv = *reinterpret_cast<const float4*>(&xs[kk][rg * 4]);
            float4 wv = *reinterpret_cast<const float4*>(&Wc[kk][cg * 4]);
            acc0.x = fmaf(xv.x, wv.x, acc0.x); acc0.y = fmaf(xv.x, wv.y, acc0.y);
            acc0.z = fmaf(xv.x, wv.z, acc0.z); acc0.w = fmaf(xv.x, wv.w, acc0.w);
            acc1.x = fmaf(xv.y, wv.x, acc1.x); acc1.y = fmaf(xv.y, wv.y, acc1.y);
            acc1.z = fmaf(xv.y, wv.z, acc1.z); acc1.w = fmaf(xv.y, wv.w, acc1.w);
            acc2.x = fmaf(xv.z, wv.x, acc2.x); acc2.y = fmaf(xv.z, wv.y, acc2.y);
            acc2.z = fmaf(xv.z, wv.z, acc2.z); acc2.w = fmaf(xv.z, wv.w, acc2.w);
            acc3.x = fmaf(xv.w, wv.x, acc3.x); acc3.y = fmaf(xv.w, wv.y, acc3.y);
            acc3.z = fmaf(xv.w, wv.z, acc3.z); acc3.w = fmaf(xv.w, wv.w, acc3.w);
        }
        __syncthreads();
    }

    // store h (4 rows x float4)
    int r0 = row0 + rg * 4;
    float4* h4 = reinterpret_cast<float4*>(d_h);
    if (r0 + 0 < N) h4[(size_t)(r0 + 0) * 16 + cg] = acc0;
    if (r0 + 1 < N) h4[(size_t)(r0 + 1) * 16 + cg] = acc1;
    if (r0 + 2 < N) h4[(size_t)(r0 + 2) * 16 + cg] = acc2;
    if (r0 + 3 < N) h4[(size_t)(r0 + 3) * 16 + cg] = acc3;

    // attention dot partials: per row, dot over this thread's 4 cols
    float4 As4 = reinterpret_cast<const float4*>(att_src)[cg];
    float4 Ad4 = reinterpret_cast<const float4*>(att_dst)[cg];
    float ps[4], pd[4];
    ps[0] = acc0.x*As4.x + acc0.y*As4.y + acc0.z*As4.z + acc0.w*As4.w;
    ps[1] = acc1.x*As4.x + acc1.y*As4.y + acc1.z*As4.z + acc1.w*As4.w;
    ps[2] = acc2.x*As4.x + acc2.y*As4.y + acc2.z*As4.z + acc2.w*As4.w;
    ps[3] = acc3.x*As4.x + acc3.y*As4.y + acc3.z*As4.z + acc3.w*As4.w;
    pd[0] = acc0.x*Ad4.x + acc0.y*Ad4.y + acc0.z*Ad4.z + acc0.w*Ad4.w;
    pd[1] = acc1.x*Ad4.x + acc1.y*Ad4.y + acc1.z*Ad4.z + acc1.w*Ad4.w;
    pd[2] = acc2.x*Ad4.x + acc2.y*Ad4.y + acc2.z*Ad4.z + acc2.w*Ad4.w;
    pd[3] = acc3.x*Ad4.x + acc3.y*Ad4.y + acc3.z*Ad4.z + acc3.w*Ad4.w;
    // reduce across the 16 col-groups (lanes sharing rg within the warp)
#pragma unroll
    for (int o = 8; o; o >>= 1) {
#pragma unroll
        for (int i = 0; i < 4; i++) {
            ps[i] += __shfl_xor_sync(0xffffffffu, ps[i], o);
            pd[i] += __shfl_xor_sync(0xffffffffu, pd[i], o);
        }
    }
    if (cg == 0) {
#pragma unroll
        for (int i = 0; i < 4; i++) {
            int gr = r0 + i;
            if (gr < N) { d_as[gr] = ps[i]; d_ad[gr] = pd[i]; }
        }
    }
}

// ---------------- kS23: finalize offsets + zero histogram --------------------
__global__ __launch_bounds__(256) void kS23_finalize(int N, int E, int nTiles)
{
    __shared__ int sh[128];
    int t = threadIdx.x;
    if (t < 128) sh[t] = (t < nTiles) ? d_bsum[t] : 0;
    __syncthreads();
    if (t == 0) {
        int run = 0;
        for (int i = 0; i < nTiles; i++) {
            int v = sh[i];
            sh[i] = run;
            run += v;
        }
    }
    __syncthreads();

    int i = blockIdx.x * blockDim.x + t;
    if (i < N) {
        int s = d_excl[i] + sh[i >> 10];
        d_start[i]  = s;
        d_cursor[i] = s;
        d_deg[i]    = 0;
    }
    if (i == 0) d_start[N] = E;
}

// ---------------- K2c: decode + weight + place --------------------------------
__global__ __launch_bounds__(256) void k2c_place(
    const void* __restrict__ ei_raw, int E, int N)
{
    int i = blockIdx.x * blockDim.x + threadIdx.x;
    if (i >= E) return;
    int s, d;
    if (d_is64) {
        const long long* p = (const long long*)ei_raw;
        s = (int)p[i];
        d = (int)p[(size_t)E + i];
    } else {
        const int* p = (const int*)ei_raw;
        s = p[i];
        d = p[(size_t)E + i];
    }
    if ((unsigned)s >= (unsigned)N) s = 0;
    if ((unsigned)d >= (unsigned)N) d = 0;

    float w = __expf(lrelu(d_as[s] + d_ad[d]));
    int p = atomicAdd(&d_cursor[d], 1);
    d_rec[p] = make_int2(s, __float_as_int(w));
}

// ---------------- K5: gather-aggregate, half-warp float4 ---------------------
__global__ __launch_bounds__(256) void k5_gather(
    float4* __restrict__ out, const float* __restrict__ bias, int N)
{
    int t = threadIdx.x;
    int warp = t >> 5, lane = t & 31;
    int half = lane >> 4;
    int hl   = lane & 15;
    int n = blockIdx.x * 8 + warp;
    if (n >= N) return;

    const float4* h4 = reinterpret_cast<const float4*>(d_h);

    float wself = __expf(lrelu(d_as[n] + d_ad[n]));
    float4 hv = h4[(size_t)n * 16 + hl];
    float4 acc;
    float wsum;
    if (half == 0) {
        acc = make_float4(wself * hv.x, wself * hv.y, wself * hv.z, wself * hv.w);
        wsum = wself;
    } else {
        acc = make_float4(0.f, 0.f, 0.f, 0.f);
        wsum = 0.f;
    }

    int beg = d_start[n], end = d_start[n + 1];
    int j = beg;
    for (; j + 4 <= end; j += 4) {
        int2 rA = d_rec[j + half];
        int2 rB = d_rec[j + 2 + half];
        float4 vA = h4[(size_t)rA.x * 16 + hl];
        float4 vB = h4[(size_t)rB.x * 16 + hl];
        float wA = __int_as_float(rA.y);
        float wB = __int_as_float(rB.y);
        acc.x = fmaf(wA, vA.x, acc.x); acc.y = fmaf(wA, vA.y, acc.y);
        acc.z = fmaf(wA, vA.z, acc.z); acc.w = fmaf(wA, vA.w, acc.w);
        acc.x = fmaf(wB, vB.x, acc.x); acc.y = fmaf(wB, vB.y, acc.y);
        acc.z = fmaf(wB, vB.z, acc.z); acc.w = fmaf(wB, vB.w, acc.w);
        wsum += wA + wB;
    }
    if (j + 2 <= end) {
        int2 r = d_rec[j + half];
        float4 v = h4[(size_t)r.x * 16 + hl];
        float w = __int_as_float(r.y);
        acc.x = fmaf(w, v.x, acc.x); acc.y = fmaf(w, v.y, acc.y);
        acc.z = fmaf(w, v.z, acc.z); acc.w = fmaf(w, v.w, acc.w);
        wsum += w;
        j += 2;
    }
    if (j < end) {
        int2 r = d_rec[j];
        float w = (half == 0) ? __int_as_float(r.y) : 0.f;
        float4 v = h4[(size_t)r.x * 16 + hl];
        acc.x = fmaf(w, v.x, acc.x); acc.y = fmaf(w, v.y, acc.y);
        acc.z = fmaf(w, v.z, acc.z); acc.w = fmaf(w, v.w, acc.w);
        wsum += w;
    }

    wsum  += __shfl_xor_sync(0xffffffffu, wsum,  16);
    acc.x += __shfl_xor_sync(0xffffffffu, acc.x, 16);
    acc.y += __shfl_xor_sync(0xffffffffu, acc.y, 16);
    acc.z += __shfl_xor_sync(0xffffffffu, acc.z, 16);
    acc.w += __shfl_xor_sync(0xffffffffu, acc.w, 16);

    if (half == 0) {
        float inv = 1.f / wsum;
        float4 b = reinterpret_cast<const float4*>(bias)[hl];
        out[(size_t)n * 16 + hl] = make_float4(acc.x * inv + b.x,
                                               acc.y * inv + b.y,
                                               acc.z * inv + b.z,
                                               acc.w * inv + b.w);
    }
}

// ---------------- launch ------------------------------------------------------
extern "C" void kernel_launch(void* const* d_in, const int* in_sizes, int n_in,
                              void* d_out, int out_size)
{
    const float* x    = (const float*)d_in[0];
    const void*  ei   = d_in[1];
    const float* W    = (const float*)d_in[2];
    const float* asrc = (const float*)d_in[3];
    const float* adst = (const float*)d_in[4];
    const float* bias = (const float*)d_in[5];
    float*       out  = (float*)d_out;

    int N = in_sizes[0] / IN_DIM;
    int E = in_sizes[1] / 2;
    int nTiles = (N + 1023) / 1024;

    k0_detect<<<1, 1>>>((const long long*)ei, N);
    k2a_hist<<<(E + 255) / 256, 256>>>(ei, E, N);
    kS1_tile_scan<<<nTiles, 1024>>>(N);
    k1_gemm<<<(N + 63) / 64, 256>>>(x, W, asrc, adst, N);   // 4th: profiled
    kS23_finalize<<<(N + 255) / 256, 256>>>(N, E, nTiles);
    k2c_place<<<(E + 255) / 256, 256>>>(ei, E, N);
    k5_gather<<<(N + 7) / 8, 256>>>((float4*)out, bias, N);
}

// round 13
// speedup vs baseline: 1.5172x; 1.0020x over previous
#include <cuda_runtime.h>
#include <cuda_bf16.h>

#define IN_DIM 128
#define OUT_DIM 64
#define N_MAX 100000
#define E_MAX 1600000
#define NEG_SLOPE 0.2f

// ---------------- scratch (static device globals: allocation-free) ----------
__device__ float d_h[(size_t)N_MAX * OUT_DIM];   // transformed features
__device__ float d_as[N_MAX];                    // h @ att_src
__device__ float d_ad[N_MAX];                    // h @ att_dst
__device__ int   d_deg[N_MAX];                   // in-degree histogram
__device__ int   d_excl[N_MAX];                  // tile-local exclusive prefix
__device__ int   d_bsum[128];                    // per-tile totals
__device__ int   d_start[N_MAX + 1];             // CSR row offsets (by dst)
__device__ int   d_cursor[N_MAX];                // placement cursors
__device__ int2  d_rec[E_MAX];                   // bucketed (src, w-as-bits)
__device__ int   d_is64;                         // edge_index dtype flag

__device__ __forceinline__ float lrelu(float v) {
    return v > 0.f ? v : NEG_SLOPE * v;
}

// ---------------- K0: detect edge_index element width ------------------------
__global__ void k0_detect(const long long* __restrict__ ei, int N)
{
    int ok64 = 1;
    for (int i = 0; i < 64; i++) {
        long long v = ei[i];
        if (v < 0 || v >= (long long)N) { ok64 = 0; break; }
    }
    d_is64 = ok64;
}

// ---------------- K2a: dst-degree histogram ----------------------------------
__global__ __launch_bounds__(256) void k2a_hist(
    const void* __restrict__ ei_raw, int E, int N)
{
    int i = blockIdx.x * blockDim.x + threadIdx.x;
    if (i >= E) return;
    int d;
    if (d_is64) {
        d = (int)((const long long*)ei_raw)[(size_t)E + i];
    } else {
        d = ((const int*)ei_raw)[(size_t)E + i];
    }
    if ((unsigned)d >= (unsigned)N) d = 0;
    atomicAdd(&d_deg[d], 1);
}

// ---------------- kS1: per-tile scan ------------------------------------------
__global__ __launch_bounds__(1024) void kS1_tile_scan(int N)
{
    __shared__ int sh[1024];
    int t = threadIdx.x;
    int gi = blockIdx.x * 1024 + t;
    int v = (gi < N) ? d_deg[gi] : 0;
    sh[t] = v;
    __syncthreads();
#pragma unroll
    for (int off = 1; off < 1024; off <<= 1) {
        int u = (t >= off) ? sh[t - off] : 0;
        __syncthreads();
        sh[t] += u;
        __syncthreads();
    }
    if (gi < N) d_excl[gi] = sh[t] - v;
    if (t == 1023) d_bsum[blockIdx.x] = sh[t];
}

// ---------------- K1: 8x8 register-tile GEMM, W in smem, x from global -------
// 256 threads: rg = t>>3 (32 groups x 8 rows = 256 rows/block), cg = t&7
// (8 groups x 8 cols = 64 cols). Per k: 2 LDS.128 + 64 FMA (32 FMA/LDS).
__global__ __launch_bounds__(256) void k1_gemm(
    const float* __restrict__ x, const float* __restrict__ W,
    const float* __restrict__ att_src, const float* __restrict__ att_dst, int N)
{
    __shared__ float Wc[IN_DIM * OUT_DIM];   // 32 KB, [k][c] row-major

    int t = threadIdx.x;
    {
        const float4* Wg = reinterpret_cast<const float4*>(W);
        float4* Ws = reinterpret_cast<float4*>(Wc);
        for (int i = t; i < IN_DIM * OUT_DIM / 4; i += 256) Ws[i] = Wg[i];
    }
    __syncthreads();

    int cg = t & 7;
    int rg = t >> 3;
    int row0 = blockIdx.x * 256 + rg * 8;

    float4 acc[8][2];
#pragma unroll
    for (int r = 0; r < 8; r++) {
        acc[r][0] = make_float4(0.f, 0.f, 0.f, 0.f);
        acc[r][1] = make_float4(0.f, 0.f, 0.f, 0.f);
    }

    const float4* x4  = reinterpret_cast<const float4*>(x);
    const float4* Wc4 = reinterpret_cast<const float4*>(Wc);

    for (int kq = 0; kq < IN_DIM / 4; kq++) {       // 32 k-quads
        float4 xr[8];
#pragma unroll
        for (int r = 0; r < 8; r++) {
            int gr = row0 + r;
            xr[r] = (gr < N) ? x4[(size_t)gr * 32 + kq]
                             : make_float4(0.f, 0.f, 0.f, 0.f);
        }
#pragma unroll
        for (int kk = 0; kk < 4; kk++) {
            int k = kq * 4 + kk;
            float4 w0 = Wc4[k * 16 + cg * 2];
            float4 w1 = Wc4[k * 16 + cg * 2 + 1];
#pragma unroll
            for (int r = 0; r < 8; r++) {
                float xv = (kk == 0) ? xr[r].x : (kk == 1) ? xr[r].y
                         : (kk == 2) ? xr[r].z : xr[r].w;
                acc[r][0].x = fmaf(xv, w0.x, acc[r][0].x);
                acc[r][0].y = fmaf(xv, w0.y, acc[r][0].y);
                acc[r][0].z = fmaf(xv, w0.z, acc[r][0].z);
                acc[r][0].w = fmaf(xv, w0.w, acc[r][0].w);
                acc[r][1].x = fmaf(xv, w1.x, acc[r][1].x);
                acc[r][1].y = fmaf(xv, w1.y, acc[r][1].y);
                acc[r][1].z = fmaf(xv, w1.z, acc[r][1].z);
                acc[r][1].w = fmaf(xv, w1.w, acc[r][1].w);
            }
        }
    }

    // store h: 8 rows x 2 float4 (lanes of equal rg are contiguous in cg)
    float4* h4 = reinterpret_cast<float4*>(d_h);
#pragma unroll
    for (int r = 0; r < 8; r++) {
        int gr = row0 + r;
        if (gr < N) {
            h4[(size_t)gr * 16 + cg * 2]     = acc[r][0];
            h4[(size_t)gr * 16 + cg * 2 + 1] = acc[r][1];
        }
    }

    // attention dots over this thread's 8 cols, reduce across the 8 cg lanes
    float4 As0 = reinterpret_cast<const float4*>(att_src)[cg * 2];
    float4 As1 = reinterpret_cast<const float4*>(att_src)[cg * 2 + 1];
    float4 Ad0 = reinterpret_cast<const float4*>(att_dst)[cg * 2];
    float4 Ad1 = reinterpret_cast<const float4*>(att_dst)[cg * 2 + 1];
    float ps[8], pd[8];
#pragma unroll
    for (int r = 0; r < 8; r++) {
        ps[r] = acc[r][0].x*As0.x + acc[r][0].y*As0.y + acc[r][0].z*As0.z + acc[r][0].w*As0.w
              + acc[r][1].x*As1.x + acc[r][1].y*As1.y + acc[r][1].z*As1.z + acc[r][1].w*As1.w;
        pd[r] = acc[r][0].x*Ad0.x + acc[r][0].y*Ad0.y + acc[r][0].z*Ad0.z + acc[r][0].w*Ad0.w
              + acc[r][1].x*Ad1.x + acc[r][1].y*Ad1.y + acc[r][1].z*Ad1.z + acc[r][1].w*Ad1.w;
    }
#pragma unroll
    for (int o = 4; o; o >>= 1) {        // cg lives in lane bits 0..2
#pragma unroll
        for (int r = 0; r < 8; r++) {
            ps[r] += __shfl_xor_sync(0xffffffffu, ps[r], o);
            pd[r] += __shfl_xor_sync(0xffffffffu, pd[r], o);
        }
    }
    if (cg == 0) {
#pragma unroll
        for (int r = 0; r < 8; r++) {
            int gr = row0 + r;
            if (gr < N) { d_as[gr] = ps[r]; d_ad[gr] = pd[r]; }
        }
    }
}

// ---------------- kS23: finalize offsets + zero histogram --------------------
__global__ __launch_bounds__(256) void kS23_finalize(int N, int E, int nTiles)
{
    __shared__ int sh[128];
    int t = threadIdx.x;
    if (t < 128) sh[t] = (t < nTiles) ? d_bsum[t] : 0;
    __syncthreads();
    if (t == 0) {
        int run = 0;
        for (int i = 0; i < nTiles; i++) {
            int v = sh[i];
            sh[i] = run;
            run += v;
        }
    }
    __syncthreads();

    int i = blockIdx.x * blockDim.x + t;
    if (i < N) {
        int s = d_excl[i] + sh[i >> 10];
        d_start[i]  = s;
        d_cursor[i] = s;
        d_deg[i]    = 0;
    }
    if (i == 0) d_start[N] = E;
}

// ---------------- K2c: decode + weight + place --------------------------------
__global__ __launch_bounds__(256) void k2c_place(
    const void* __restrict__ ei_raw, int E, int N)
{
    int i = blockIdx.x * blockDim.x + threadIdx.x;
    if (i >= E) return;
    int s, d;
    if (d_is64) {
        const long long* p = (const long long*)ei_raw;
        s = (int)p[i];
        d = (int)p[(size_t)E + i];
    } else {
        const int* p = (const int*)ei_raw;
        s = p[i];
        d = p[(size_t)E + i];
    }
    if ((unsigned)s >= (unsigned)N) s = 0;
    if ((unsigned)d >= (unsigned)N) d = 0;

    float w = __expf(lrelu(d_as[s] + d_ad[d]));
    int p = atomicAdd(&d_cursor[d], 1);
    d_rec[p] = make_int2(s, __float_as_int(w));
}

// ---------------- K5: gather-aggregate, half-warp float4 ---------------------
__global__ __launch_bounds__(256) void k5_gather(
    float4* __restrict__ out, const float* __restrict__ bias, int N)
{
    int t = threadIdx.x;
    int warp = t >> 5, lane = t & 31;
    int half = lane >> 4;
    int hl   = lane & 15;
    int n = blockIdx.x * 8 + warp;
    if (n >= N) return;

    const float4* h4 = reinterpret_cast<const float4*>(d_h);

    float wself = __expf(lrelu(d_as[n] + d_ad[n]));
    float4 hv = h4[(size_t)n * 16 + hl];
    float4 acc;
    float wsum;
    if (half == 0) {
        acc = make_float4(wself * hv.x, wself * hv.y, wself * hv.z, wself * hv.w);
        wsum = wself;
    } else {
        acc = make_float4(0.f, 0.f, 0.f, 0.f);
        wsum = 0.f;
    }

    int beg = d_start[n], end = d_start[n + 1];
    int j = beg;
    for (; j + 4 <= end; j += 4) {
        int2 rA = d_rec[j + half];
        int2 rB = d_rec[j + 2 + half];
        float4 vA = h4[(size_t)rA.x * 16 + hl];
        float4 vB = h4[(size_t)rB.x * 16 + hl];
        float wA = __int_as_float(rA.y);
        float wB = __int_as_float(rB.y);
        acc.x = fmaf(wA, vA.x, acc.x); acc.y = fmaf(wA, vA.y, acc.y);
        acc.z = fmaf(wA, vA.z, acc.z); acc.w = fmaf(wA, vA.w, acc.w);
        acc.x = fmaf(wB, vB.x, acc.x); acc.y = fmaf(wB, vB.y, acc.y);
        acc.z = fmaf(wB, vB.z, acc.z); acc.w = fmaf(wB, vB.w, acc.w);
        wsum += wA + wB;
    }
    if (j + 2 <= end) {
        int2 r = d_rec[j + half];
        float4 v = h4[(size_t)r.x * 16 + hl];
        float w = __int_as_float(r.y);
        acc.x = fmaf(w, v.x, acc.x); acc.y = fmaf(w, v.y, acc.y);
        acc.z = fmaf(w, v.z, acc.z); acc.w = fmaf(w, v.w, acc.w);
        wsum += w;
        j += 2;
    }
    if (j < end) {
        int2 r = d_rec[j];
        float w = (half == 0) ? __int_as_float(r.y) : 0.f;
        float4 v = h4[(size_t)r.x * 16 + hl];
        acc.x = fmaf(w, v.x, acc.x); acc.y = fmaf(w, v.y, acc.y);
        acc.z = fmaf(w, v.z, acc.z); acc.w = fmaf(w, v.w, acc.w);
        wsum += w;
    }

    wsum  += __shfl_xor_sync(0xffffffffu, wsum,  16);
    acc.x += __shfl_xor_sync(0xffffffffu, acc.x, 16);
    acc.y += __shfl_xor_sync(0xffffffffu, acc.y, 16);
    acc.z += __shfl_xor_sync(0xffffffffu, acc.z, 16);
    acc.w += __shfl_xor_sync(0xffffffffu, acc.w, 16);

    if (half == 0) {
        float inv = 1.f / wsum;
        float4 b = reinterpret_cast<const float4*>(bias)[hl];
        out[(size_t)n * 16 + hl] = make_float4(acc.x * inv + b.x,
                                               acc.y * inv + b.y,
                                               acc.z * inv + b.z,
                                               acc.w * inv + b.w);
    }
}

// ---------------- launch ------------------------------------------------------
extern "C" void kernel_launch(void* const* d_in, const int* in_sizes, int n_in,
                              void* d_out, int out_size)
{
    const float* x    = (const float*)d_in[0];
    const void*  ei   = d_in[1];
    const float* W    = (const float*)d_in[2];
    const float* asrc = (const float*)d_in[3];
    const float* adst = (const float*)d_in[4];
    const float* bias = (const float*)d_in[5];
    float*       out  = (float*)d_out;

    int N = in_sizes[0] / IN_DIM;
    int E = in_sizes[1] / 2;
    int nTiles = (N + 1023) / 1024;

    k0_detect<<<1, 1>>>((const long long*)ei, N);
    k2a_hist<<<(E + 255) / 256, 256>>>(ei, E, N);
    kS1_tile_scan<<<nTiles, 1024>>>(N);
    k1_gemm<<<(N + 255) / 256, 256>>>(x, W, asrc, adst, N);   // 4th: profiled
    kS23_finalize<<<(N + 255) / 256, 256>>>(N, E, nTiles);
    k2c_place<<<(E + 255) / 256, 256>>>(ei, E, N);
    k5_gather<<<(N + 7) / 8, 256>>>((float4*)out, bias, N);
}